// round 15
// baseline (speedup 1.0000x reference)
#include <cuda_runtime.h>
#include <cstdint>

// LocalAttention: 7x7 windowed MHA + depthwise-3x3 LePE on V.
// grid (4096, 12), 64 threads (8 ti x 8 tj). fp32 via fma.rn.f32x2.
// R14 = R13 (500us) + duplicated-q storage (qd[49][64] of (q,q) pairs) so
//       phase 1 has ZERO pack MOVs; kT swizzle dropped (KS=52) to fit smem.

typedef unsigned long long u64;

#define QDS 64   // duplicated-q row stride (32 d -> 32 u64 pairs)
#define VS  36   // v token-major row stride (144B, cp.async-aligned)
#define KS  52   // kT row stride (cols 49..51 + spill reads: garbage, masked)
#define SS  52   // expS row stride

__device__ __forceinline__ u64 pack2(float lo, float hi) {
    u64 r; asm("mov.b64 %0, {%1, %2};" : "=l"(r) : "f"(lo), "f"(hi)); return r;
}
__device__ __forceinline__ void unpack2(u64 v, float &lo, float &hi) {
    asm("mov.b64 {%0, %1}, %2;" : "=f"(lo), "=f"(hi) : "l"(v));
}
__device__ __forceinline__ u64 ffma2(u64 a, u64 b, u64 c) {
    u64 d; asm("fma.rn.f32x2 %0, %1, %2, %3;" : "=l"(d) : "l"(a), "l"(b), "l"(c));
    return d;
}
__device__ __forceinline__ float ex2(float x) {
    float y; asm("ex2.approx.ftz.f32 %0, %1;" : "=f"(y) : "f"(x)); return y;
}
__device__ __forceinline__ float rcp(float x) {
    float y; asm("rcp.approx.ftz.f32 %0, %1;" : "=f"(y) : "f"(x)); return y;
}
__device__ __forceinline__ uint32_t smem_u32(const void* p) {
    uint32_t a;
    asm("{ .reg .u64 t; cvta.to.shared.u64 t, %1; cvt.u32.u64 %0, t; }"
        : "=r"(a) : "l"(p));
    return a;
}
__device__ __forceinline__ void cpa16(uint32_t dst, const void* src) {
    asm volatile("cp.async.ca.shared.global [%0], [%1], 16;" :: "r"(dst), "l"(src));
}
__device__ __forceinline__ void cpa4(uint32_t dst, const void* src) {
    asm volatile("cp.async.ca.shared.global [%0], [%1], 4;" :: "r"(dst), "l"(src));
}

__global__ __launch_bounds__(64, 8)
void la_kernel(const float* __restrict__ qkv,
               const float* __restrict__ cw,
               const float* __restrict__ cb,
               float* __restrict__ out)
{
    // floats: [0,4800) = union{ qd[49*64]+kT[32*52] | S[49*52] }
    __shared__ __align__(16) float sm[6884];
    float* qd  = sm;            // [49][QDS] duplicated (q,q) pairs
    float* kT  = sm + 3136;     // [32][KS]  d-major, scaled, plain transpose
    float* S   = sm;            // [49][SS]  aliases qd-head after phase 1
    float* vsm = sm + 4800;     // [49][VS]
    float* wsm = sm + 6564;     // [9][32]
    float* bsm = sm + 6852;     // [32]

    const int tid = threadIdx.x;
    const int h   = blockIdx.y;
    const int win = blockIdx.x;
    const int b   = win >> 8;
    const int wy  = (win >> 4) & 15;
    const int wx  = win & 15;
    const int tok0  = b * 12544 + wy * 784 + wx * 7;
    const int cbase = h * 32;

    // 1/sqrt(32) * log2(e), folded into K during transpose-store
    const float scale = 0.17677669529663687f * 1.4426950408889634f;
    const size_t koff4 = 19267584ull;           // B*L*DIM/4 (float4 units)

    const uint32_t vsm_a = smem_u32(vsm);
    const uint32_t wsm_a = smem_u32(wsm);
    const uint32_t bsm_a = smem_u32(bsm);

    // ---- prologue: v via cp.async; q duplicated; k scaled transpose ----
    const float4* qkv4 = (const float4*)qkv;
    for (int idx = tid; idx < 392; idx += 64) {
        int tok = idx >> 3, w = idx & 7;        // d = 4w..4w+3
        int ly = tok / 7, lx = tok - ly * 7;
        size_t g = (size_t)(tok0 + ly * 112 + lx) * 96 + h * 8 + w;
        cpa16(vsm_a + (uint32_t)(tok * VS + 4 * w) * 4u, qkv4 + g + 2 * koff4);
        float4 q4 = qkv4[g];
        float4 k4 = qkv4[g + koff4];
        // duplicated q: (x,x,y,y) and (z,z,w,w)
        float* qrow = qd + tok * QDS + 8 * w;
        *(float4*)(qrow)     = make_float4(q4.x, q4.x, q4.y, q4.y);
        *(float4*)(qrow + 4) = make_float4(q4.z, q4.z, q4.w, q4.w);
        // k transpose (plain), scale folded in
        int d0 = 4 * w;
        kT[(d0    ) * KS + tok] = k4.x * scale;
        kT[(d0 + 1) * KS + tok] = k4.y * scale;
        kT[(d0 + 2) * KS + tok] = k4.z * scale;
        kT[(d0 + 3) * KS + tok] = k4.w * scale;
    }
    for (int idx = tid; idx < 288; idx += 64) {
        int tap = idx >> 5, d = idx & 31;
        cpa4(wsm_a + (uint32_t)(tap * 32 + d) * 4u, cw + (cbase + d) * 9 + tap);
    }
    if (tid < 32) cpa4(bsm_a + tid * 4u, cb + cbase + tid);
    asm volatile("cp.async.commit_group;");
    asm volatile("cp.async.wait_group 0;" ::: "memory");
    __syncthreads();

    const int ti = tid >> 3;   // 0..7 (rows 7ti..7ti+6; ti==7 pad lane)
    const int tj = tid & 7;    // cols 4tj+{0..3}, 4tj+32+{0..3}
    const int rbase = (ti < 7) ? 7 * ti : 42;   // clamp pad lanes

    // ---- phase 1: S = q @ (k*scale)^T, zero packs (q pre-duplicated) ----
    u64 acc[7][4];
    #pragma unroll
    for (int r = 0; r < 7; r++)
        #pragma unroll
        for (int p = 0; p < 4; p++) acc[r][p] = 0ull;

    {
        const float* qb = qd + rbase * QDS;
        const float* kb = kT + (tj << 2);
        #pragma unroll
        for (int dg = 0; dg < 8; dg++) {
            // k for 4 consecutive d rows (cols 4tj.. and 4tj+32..)
            ulonglong2 ka0 = *(const ulonglong2*)(kb + (4 * dg    ) * KS);
            ulonglong2 kc0 = *(const ulonglong2*)(kb + (4 * dg    ) * KS + 32);
            ulonglong2 ka1 = *(const ulonglong2*)(kb + (4 * dg + 1) * KS);
            ulonglong2 kc1 = *(const ulonglong2*)(kb + (4 * dg + 1) * KS + 32);
            ulonglong2 ka2 = *(const ulonglong2*)(kb + (4 * dg + 2) * KS);
            ulonglong2 kc2 = *(const ulonglong2*)(kb + (4 * dg + 2) * KS + 32);
            ulonglong2 ka3 = *(const ulonglong2*)(kb + (4 * dg + 3) * KS);
            ulonglong2 kc3 = *(const ulonglong2*)(kb + (4 * dg + 3) * KS + 32);
            #pragma unroll
            for (int r = 0; r < 7; r++) {
                const float* qr = qb + r * QDS + 8 * dg;
                ulonglong2 A = *(const ulonglong2*)(qr);      // (q0,q0),(q1,q1)
                ulonglong2 B = *(const ulonglong2*)(qr + 4);  // (q2,q2),(q3,q3)
                acc[r][0] = ffma2(A.x, ka0.x, acc[r][0]);
                acc[r][1] = ffma2(A.x, ka0.y, acc[r][1]);
                acc[r][2] = ffma2(A.x, kc0.x, acc[r][2]);
                acc[r][3] = ffma2(A.x, kc0.y, acc[r][3]);
                acc[r][0] = ffma2(A.y, ka1.x, acc[r][0]);
                acc[r][1] = ffma2(A.y, ka1.y, acc[r][1]);
                acc[r][2] = ffma2(A.y, kc1.x, acc[r][2]);
                acc[r][3] = ffma2(A.y, kc1.y, acc[r][3]);
                acc[r][0] = ffma2(B.x, ka2.x, acc[r][0]);
                acc[r][1] = ffma2(B.x, ka2.y, acc[r][1]);
                acc[r][2] = ffma2(B.x, kc2.x, acc[r][2]);
                acc[r][3] = ffma2(B.x, kc2.y, acc[r][3]);
                acc[r][0] = ffma2(B.y, ka3.x, acc[r][0]);
                acc[r][1] = ffma2(B.y, ka3.y, acc[r][1]);
                acc[r][2] = ffma2(B.y, kc3.x, acc[r][2]);
                acc[r][3] = ffma2(B.y, kc3.y, acc[r][3]);
            }
        }
    }
    __syncthreads();   // qd/kT reads done (all warps); S may overwrite

    // ---- softmax: no max subtraction, normalized store ----
    // garbage cols (>=49, incl. cross-row spill reads) land in masked lanes.
    {
        const int c1 = 4 * tj + 32;
        #pragma unroll
        for (int r = 0; r < 7; r++) {
            float s0, s1, s2, s3, s4, s5, s6, s7;
            unpack2(acc[r][0], s0, s1);
            unpack2(acc[r][1], s2, s3);
            unpack2(acc[r][2], s4, s5);
            unpack2(acc[r][3], s6, s7);
            if (c1     >= 49) s4 = -1e30f;   // ex2 -> exact 0
            if (c1 + 1 >= 49) s5 = -1e30f;
            if (c1 + 2 >= 49) s6 = -1e30f;
            if (c1 + 3 >= 49) s7 = -1e30f;
            float e0 = ex2(s0), e1 = ex2(s1);
            float e2 = ex2(s2), e3 = ex2(s3);
            float e4 = ex2(s4), e5 = ex2(s5);
            float e6 = ex2(s6), e7 = ex2(s7);
            float sum = ((e0 + e1) + (e2 + e3)) + ((e4 + e5) + (e6 + e7));
            sum += __shfl_xor_sync(0xffffffffu, sum, 1);
            sum += __shfl_xor_sync(0xffffffffu, sum, 2);
            sum += __shfl_xor_sync(0xffffffffu, sum, 4);
            float iv = rcp(sum);
            if (ti < 7) {
                float* srow = S + (7 * ti + r) * SS;
                *(u64*)(srow + 4 * tj)     = pack2(e0 * iv, e1 * iv);
                *(u64*)(srow + 4 * tj + 2) = pack2(e2 * iv, e3 * iv);
                if (c1 < SS) {   // tj<=4: cols 32..51 (49..51 get zeros)
                    *(u64*)(srow + c1)     = pack2(e4 * iv, e5 * iv);
                    *(u64*)(srow + c1 + 2) = pack2(e6 * iv, e7 * iv);
                }
            }
        }
    }
    // S rows for this thread are produced by lanes of the SAME warp only
    __syncwarp();

    // ---- phase 2: out = S @ V + LePE(V) + bias ----
    {
        u64 att[7][2];
        float4 bb = *(const float4*)(bsm + tj * 4);
        u64 b01 = pack2(bb.x, bb.y), b23 = pack2(bb.z, bb.w);
        #pragma unroll
        for (int r = 0; r < 7; r++) { att[r][0] = b01; att[r][1] = b23; }

        // LePE with per-ny v-row register cache (7 rows loaded once per ky)
        #pragma unroll
        for (int ky = 0; ky < 3; ky++) {
            int ny = ti + ky - 1;
            if (ny >= 0 && ny <= 6) {
                ulonglong2 vc[7];
                #pragma unroll
                for (int rr = 0; rr < 7; rr++)
                    vc[rr] = *(const ulonglong2*)(vsm + (ny * 7 + rr) * VS + tj * 4);
                #pragma unroll
                for (int kx = 0; kx < 3; kx++) {
                    const ulonglong2 w2 =
                        *(const ulonglong2*)(wsm + (ky * 3 + kx) * 32 + tj * 4);
                    #pragma unroll
                    for (int r = 0; r < 7; r++) {
                        int nx = r + kx - 1;
                        if (nx >= 0 && nx <= 6) {
                            att[r][0] = ffma2(w2.x, vc[nx].x, att[r][0]);
                            att[r][1] = ffma2(w2.y, vc[nx].y, att[r][1]);
                        }
                    }
                }
            }
        }

        // attention: k = 0..47 in 12 float4 groups (S already normalized)
        const float* Sb = S + rbase * SS;
        const float* vb = vsm + (tj << 2);
        #pragma unroll
        for (int kg = 0; kg < 12; kg++) {
            ulonglong2 v0 = *(const ulonglong2*)(vb + (4 * kg    ) * VS);
            ulonglong2 v1 = *(const ulonglong2*)(vb + (4 * kg + 1) * VS);
            ulonglong2 v2 = *(const ulonglong2*)(vb + (4 * kg + 2) * VS);
            ulonglong2 v3 = *(const ulonglong2*)(vb + (4 * kg + 3) * VS);
            #pragma unroll
            for (int r = 0; r < 7; r++) {
                float4 s4 = *(const float4*)(Sb + r * SS + 4 * kg);
                u64 p;
                p = pack2(s4.x, s4.x);
                att[r][0] = ffma2(p, v0.x, att[r][0]);
                att[r][1] = ffma2(p, v0.y, att[r][1]);
                p = pack2(s4.y, s4.y);
                att[r][0] = ffma2(p, v1.x, att[r][0]);
                att[r][1] = ffma2(p, v1.y, att[r][1]);
                p = pack2(s4.z, s4.z);
                att[r][0] = ffma2(p, v2.x, att[r][0]);
                att[r][1] = ffma2(p, v2.y, att[r][1]);
                p = pack2(s4.w, s4.w);
                att[r][0] = ffma2(p, v3.x, att[r][0]);
                att[r][1] = ffma2(p, v3.y, att[r][1]);
            }
        }
        // tail: k = 48
        {
            ulonglong2 vt = *(const ulonglong2*)(vb + 48 * VS);
            #pragma unroll
            for (int r = 0; r < 7; r++) {
                float s = Sb[r * SS + 48];
                u64 p = pack2(s, s);
                att[r][0] = ffma2(p, vt.x, att[r][0]);
                att[r][1] = ffma2(p, vt.y, att[r][1]);
            }
        }

        if (ti < 7) {
            #pragma unroll
            for (int r = 0; r < 7; r++) {
                float4 o;
                unpack2(att[r][0], o.x, o.y);
                unpack2(att[r][1], o.z, o.w);
                *(float4*)(out + (size_t)(tok0 + ti * 112 + r) * 384 + cbase + tj * 4) = o;
            }
        }
    }
}

extern "C" void kernel_launch(void* const* d_in, const int* in_sizes, int n_in,
                              void* d_out, int out_size)
{
    const float* qkv = (const float*)d_in[0];
    const float* cw  = (const float*)d_in[1];
    const float* cb  = (const float*)d_in[2];
    float* o = (float*)d_out;
    dim3 grid(4096, 12, 1);
    la_kernel<<<grid, 64>>>(qkv, cw, cb, o);
}

// round 16
// speedup vs baseline: 1.1590x; 1.1590x over previous
#include <cuda_runtime.h>
#include <cstdint>

// LocalAttention: 7x7 windowed MHA + depthwise-3x3 LePE on V.
// grid (4096, 12), 64 threads (8 ti x 8 tj). fp32 via fma.rn.f32x2.
// R15 = R13 (500us) + de-padded phase 1: group B is 2 cols/lane
//       (32+2tj..33+2tj covers 32..47, zero waste), col 48 via d-split
//       shfl reduce. No masking anywhere; -224 ffma2/thread.

typedef unsigned long long u64;

#define QVS 36   // q / v token-major row stride (144B, cp.async-aligned)
#define KS  64   // kT row stride (16 blocks of 16B, XOR-swizzled)
#define SS  52   // expS row stride

__device__ __forceinline__ u64 pack2(float lo, float hi) {
    u64 r; asm("mov.b64 %0, {%1, %2};" : "=l"(r) : "f"(lo), "f"(hi)); return r;
}
__device__ __forceinline__ void unpack2(u64 v, float &lo, float &hi) {
    asm("mov.b64 {%0, %1}, %2;" : "=f"(lo), "=f"(hi) : "l"(v));
}
__device__ __forceinline__ u64 ffma2(u64 a, u64 b, u64 c) {
    u64 d; asm("fma.rn.f32x2 %0, %1, %2, %3;" : "=l"(d) : "l"(a), "l"(b), "l"(c));
    return d;
}
__device__ __forceinline__ float ex2(float x) {
    float y; asm("ex2.approx.ftz.f32 %0, %1;" : "=f"(y) : "f"(x)); return y;
}
__device__ __forceinline__ float rcp(float x) {
    float y; asm("rcp.approx.ftz.f32 %0, %1;" : "=f"(y) : "f"(x)); return y;
}
__device__ __forceinline__ uint32_t smem_u32(const void* p) {
    uint32_t a;
    asm("{ .reg .u64 t; cvta.to.shared.u64 t, %1; cvt.u32.u64 %0, t; }"
        : "=r"(a) : "l"(p));
    return a;
}
__device__ __forceinline__ void cpa16(uint32_t dst, const void* src) {
    asm volatile("cp.async.ca.shared.global [%0], [%1], 16;" :: "r"(dst), "l"(src));
}
__device__ __forceinline__ void cpa4(uint32_t dst, const void* src) {
    asm volatile("cp.async.ca.shared.global [%0], [%1], 4;" :: "r"(dst), "l"(src));
}

__global__ __launch_bounds__(64, 8)
void la_kernel(const float* __restrict__ qkv,
               const float* __restrict__ cw,
               const float* __restrict__ cb,
               float* __restrict__ out)
{
    // floats: [0,3812) = union{ qsm[49*36]+kT[32*64] | S[49*52] }
    __shared__ __align__(16) float sm[5896];
    float* qsm = sm;            // [49][QVS] token-major (raw q; scale on k)
    float* kT  = sm + 1764;     // [32][KS]  d-major, token blocks XOR-swizzled
    float* S   = sm;            // [49][SS]  aliases qsm/kT-head after phase 1
    float* vsm = sm + 3812;     // [49][QVS]
    float* wsm = sm + 5576;     // [9][32]
    float* bsm = sm + 5864;     // [32]

    const int tid = threadIdx.x;
    const int h   = blockIdx.y;
    const int win = blockIdx.x;
    const int b   = win >> 8;
    const int wy  = (win >> 4) & 15;
    const int wx  = win & 15;
    const int tok0  = b * 12544 + wy * 784 + wx * 7;
    const int cbase = h * 32;

    // 1/sqrt(32) * log2(e), folded into K during transpose-store
    const float scale = 0.17677669529663687f * 1.4426950408889634f;
    const size_t koff4 = 19267584ull;           // B*L*DIM/4 (float4 units)

    const uint32_t vsm_a = smem_u32(vsm);
    const uint32_t wsm_a = smem_u32(wsm);
    const uint32_t bsm_a = smem_u32(bsm);

    // ---- prologue: q,v via cp.async; k via LDG + scaled swizzled STS ----
    const float4* qkv4 = (const float4*)qkv;
    const uint32_t qsm_a = smem_u32(qsm);
    for (int idx = tid; idx < 392; idx += 64) {
        int tok = idx >> 3, w = idx & 7;        // d = 4w..4w+3
        int ly = tok / 7, lx = tok - ly * 7;
        size_t g = (size_t)(tok0 + ly * 112 + lx) * 96 + h * 8 + w;
        uint32_t soff = (uint32_t)(tok * QVS + 4 * w) * 4u;
        cpa16(qsm_a + soff, qkv4 + g);                 // q raw
        cpa16(vsm_a + soff, qkv4 + g + 2 * koff4);     // v raw
        float4 k4 = qkv4[g + koff4];
        int d0 = 4 * w;
        // swizzled kT store: key = (d>>2)&3 = w&3 for all 4 components
        int pcol = ((((tok >> 2) ^ (w & 3)) << 2)) | (tok & 3);
        kT[(d0    ) * KS + pcol] = k4.x * scale;
        kT[(d0 + 1) * KS + pcol] = k4.y * scale;
        kT[(d0 + 2) * KS + pcol] = k4.z * scale;
        kT[(d0 + 3) * KS + pcol] = k4.w * scale;
    }
    for (int idx = tid; idx < 288; idx += 64) {
        int tap = idx >> 5, d = idx & 31;
        cpa4(wsm_a + (uint32_t)(tap * 32 + d) * 4u, cw + (cbase + d) * 9 + tap);
    }
    if (tid < 32) cpa4(bsm_a + tid * 4u, cb + cbase + tid);
    asm volatile("cp.async.commit_group;");
    asm volatile("cp.async.wait_group 0;" ::: "memory");
    __syncthreads();

    const int ti = tid >> 3;   // 0..7 (rows 7ti..7ti+6; ti==7 pad lane)
    const int tj = tid & 7;    // A cols 4tj..4tj+3; B cols 32+2tj..33+2tj
    const int rbase = (ti < 7) ? 7 * ti : 42;   // clamp pad lanes into qsm

    // ---- phase 1: S = q @ (k*scale)^T, cols 0..47, acc in regs ----
    u64 acc[7][3];   // [0]: cols 4tj,4tj+1  [1]: 4tj+2,4tj+3  [2]: 32+2tj,33+2tj
    #pragma unroll
    for (int r = 0; r < 7; r++)
        #pragma unroll
        for (int p = 0; p < 3; p++) acc[r][p] = 0ull;

    const float* qb = qsm + rbase * QVS;
    {
        const int bblk = 8 + (tj >> 1);         // logical 16B block of B col
        const int boff = (2 * tj) & 3;          // float offset within block
        #pragma unroll
        for (int dg = 0; dg < 8; dg++) {
            float4 q4[7];
            #pragma unroll
            for (int r = 0; r < 7; r++)
                q4[r] = *(const float4*)(qb + r * QVS + 4 * dg);
            const int key = dg & 3;
            const float* kbA = kT + ((tj ^ key) << 2);
            const float* kbB = kT + ((bblk ^ key) << 2) + boff;
            #pragma unroll
            for (int dd = 0; dd < 4; dd++) {
                const int drow = (4 * dg + dd) * KS;
                ulonglong2 ka = *(const ulonglong2*)(kbA + drow);
                u64 kb8 = *(const u64*)(kbB + drow);
                #pragma unroll
                for (int r = 0; r < 7; r++) {
                    float qv = (dd == 0) ? q4[r].x : (dd == 1) ? q4[r].y
                             : (dd == 2) ? q4[r].z : q4[r].w;
                    u64 q2 = pack2(qv, qv);
                    acc[r][0] = ffma2(q2, ka.x, acc[r][0]);
                    acc[r][1] = ffma2(q2, ka.y, acc[r][1]);
                    acc[r][2] = ffma2(q2, kb8, acc[r][2]);
                }
            }
        }
    }

    // ---- col 48: d-split across the 8 tj lanes, shfl reduce ----
    float s48[7];
    {
        const float* kc = kT + ((12 ^ (tj & 3)) << 2);   // logical block 12
        float k0 = kc[(4 * tj    ) * KS];
        float k1 = kc[(4 * tj + 1) * KS];
        float k2 = kc[(4 * tj + 2) * KS];
        float k3 = kc[(4 * tj + 3) * KS];
        #pragma unroll
        for (int r = 0; r < 7; r++) {
            float4 qq = *(const float4*)(qb + r * QVS + 4 * tj);
            float p = qq.x * k0 + qq.y * k1 + qq.z * k2 + qq.w * k3;
            p += __shfl_xor_sync(0xffffffffu, p, 1);
            p += __shfl_xor_sync(0xffffffffu, p, 2);
            p += __shfl_xor_sync(0xffffffffu, p, 4);
            s48[r] = p;
        }
    }
    __syncthreads();   // qsm/kT reads done (all warps); S may overwrite

    // ---- softmax: no max subtraction, no masking, normalized store ----
    {
        #pragma unroll
        for (int r = 0; r < 7; r++) {
            float s0, s1, s2, s3, s4, s5;
            unpack2(acc[r][0], s0, s1);
            unpack2(acc[r][1], s2, s3);
            unpack2(acc[r][2], s4, s5);
            float e0 = ex2(s0), e1 = ex2(s1);
            float e2 = ex2(s2), e3 = ex2(s3);
            float e4 = ex2(s4), e5 = ex2(s5);
            float e48 = ex2(s48[r]);
            float sum = ((e0 + e1) + (e2 + e3)) + (e4 + e5);
            sum += __shfl_xor_sync(0xffffffffu, sum, 1);
            sum += __shfl_xor_sync(0xffffffffu, sum, 2);
            sum += __shfl_xor_sync(0xffffffffu, sum, 4);
            sum += e48;                       // col 48, counted once
            float iv = rcp(sum);
            if (ti < 7) {
                float* srow = S + (7 * ti + r) * SS;
                *(u64*)(srow + 4 * tj)      = pack2(e0 * iv, e1 * iv);
                *(u64*)(srow + 4 * tj + 2)  = pack2(e2 * iv, e3 * iv);
                *(u64*)(srow + 32 + 2 * tj) = pack2(e4 * iv, e5 * iv);
                if (tj == 0) srow[48] = e48 * iv;
            }
        }
    }
    // S rows for this thread are produced by lanes of the SAME warp only
    __syncwarp();

    // ---- phase 2: out = S @ V + LePE(V) + bias ----
    {
        u64 att[7][2];
        float4 bb = *(const float4*)(bsm + tj * 4);
        u64 b01 = pack2(bb.x, bb.y), b23 = pack2(bb.z, bb.w);
        #pragma unroll
        for (int r = 0; r < 7; r++) { att[r][0] = b01; att[r][1] = b23; }

        // LePE with per-ny v-row register cache (7 rows loaded once per ky)
        #pragma unroll
        for (int ky = 0; ky < 3; ky++) {
            int ny = ti + ky - 1;
            if (ny >= 0 && ny <= 6) {
                ulonglong2 vc[7];
                #pragma unroll
                for (int rr = 0; rr < 7; rr++)
                    vc[rr] = *(const ulonglong2*)(vsm + (ny * 7 + rr) * QVS + tj * 4);
                #pragma unroll
                for (int kx = 0; kx < 3; kx++) {
                    const ulonglong2 w2 =
                        *(const ulonglong2*)(wsm + (ky * 3 + kx) * 32 + tj * 4);
                    #pragma unroll
                    for (int r = 0; r < 7; r++) {
                        int nx = r + kx - 1;
                        if (nx >= 0 && nx <= 6) {
                            att[r][0] = ffma2(w2.x, vc[nx].x, att[r][0]);
                            att[r][1] = ffma2(w2.y, vc[nx].y, att[r][1]);
                        }
                    }
                }
            }
        }

        // attention: k = 0..47 in 12 float4 groups (S already normalized)
        const float* Sb = S + rbase * SS;
        const float* vb = vsm + (tj << 2);
        #pragma unroll
        for (int kg = 0; kg < 12; kg++) {
            ulonglong2 v0 = *(const ulonglong2*)(vb + (4 * kg    ) * QVS);
            ulonglong2 v1 = *(const ulonglong2*)(vb + (4 * kg + 1) * QVS);
            ulonglong2 v2 = *(const ulonglong2*)(vb + (4 * kg + 2) * QVS);
            ulonglong2 v3 = *(const ulonglong2*)(vb + (4 * kg + 3) * QVS);
            #pragma unroll
            for (int r = 0; r < 7; r++) {
                float4 s4 = *(const float4*)(Sb + r * SS + 4 * kg);
                u64 p;
                p = pack2(s4.x, s4.x);
                att[r][0] = ffma2(p, v0.x, att[r][0]);
                att[r][1] = ffma2(p, v0.y, att[r][1]);
                p = pack2(s4.y, s4.y);
                att[r][0] = ffma2(p, v1.x, att[r][0]);
                att[r][1] = ffma2(p, v1.y, att[r][1]);
                p = pack2(s4.z, s4.z);
                att[r][0] = ffma2(p, v2.x, att[r][0]);
                att[r][1] = ffma2(p, v2.y, att[r][1]);
                p = pack2(s4.w, s4.w);
                att[r][0] = ffma2(p, v3.x, att[r][0]);
                att[r][1] = ffma2(p, v3.y, att[r][1]);
            }
        }
        // tail: k = 48
        {
            ulonglong2 vt = *(const ulonglong2*)(vb + 48 * QVS);
            #pragma unroll
            for (int r = 0; r < 7; r++) {
                float s = Sb[r * SS + 48];
                u64 p = pack2(s, s);
                att[r][0] = ffma2(p, vt.x, att[r][0]);
                att[r][1] = ffma2(p, vt.y, att[r][1]);
            }
        }

        if (ti < 7) {
            #pragma unroll
            for (int r = 0; r < 7; r++) {
                float4 o;
                unpack2(att[r][0], o.x, o.y);
                unpack2(att[r][1], o.z, o.w);
                *(float4*)(out + (size_t)(tok0 + ti * 112 + r) * 384 + cbase + tj * 4) = o;
            }
        }
    }
}

extern "C" void kernel_launch(void* const* d_in, const int* in_sizes, int n_in,
                              void* d_out, int out_size)
{
    const float* qkv = (const float*)d_in[0];
    const float* cw  = (const float*)d_in[1];
    const float* cb  = (const float*)d_in[2];
    float* o = (float*)d_out;
    dim3 grid(4096, 12, 1);
    la_kernel<<<grid, 64>>>(qkv, cw, cb, o);
}

// round 17
// speedup vs baseline: 1.3405x; 1.1566x over previous
#include <cuda_runtime.h>
#include <cstdint>

// LocalAttention: 7x7 windowed MHA + depthwise-3x3 LePE on V.
// grid (4096, 12), 64 threads (8 ti x 8 tj). fp32 via fma.rn.f32x2.
// R16 = R15 (477us) + incremental prologue addressing (no div/mod in loop)
//       + packed softmax normalize (mul2 on pairs) + float4 A-store
//       + direct ulonglong2 epilogue store.

typedef unsigned long long u64;

#define QVS 36   // q / v token-major row stride (144B, cp.async-aligned)
#define KS  64   // kT row stride (16 blocks of 16B, XOR-swizzled)
#define SS  52   // expS row stride

__device__ __forceinline__ u64 pack2(float lo, float hi) {
    u64 r; asm("mov.b64 %0, {%1, %2};" : "=l"(r) : "f"(lo), "f"(hi)); return r;
}
__device__ __forceinline__ void unpack2(u64 v, float &lo, float &hi) {
    asm("mov.b64 {%0, %1}, %2;" : "=f"(lo), "=f"(hi) : "l"(v));
}
__device__ __forceinline__ u64 ffma2(u64 a, u64 b, u64 c) {
    u64 d; asm("fma.rn.f32x2 %0, %1, %2, %3;" : "=l"(d) : "l"(a), "l"(b), "l"(c));
    return d;
}
__device__ __forceinline__ u64 mul2(u64 a, u64 b) {
    u64 d; asm("mul.rn.f32x2 %0, %1, %2;" : "=l"(d) : "l"(a), "l"(b));
    return d;
}
__device__ __forceinline__ float ex2(float x) {
    float y; asm("ex2.approx.ftz.f32 %0, %1;" : "=f"(y) : "f"(x)); return y;
}
__device__ __forceinline__ float rcp(float x) {
    float y; asm("rcp.approx.ftz.f32 %0, %1;" : "=f"(y) : "f"(x)); return y;
}
__device__ __forceinline__ uint32_t smem_u32(const void* p) {
    uint32_t a;
    asm("{ .reg .u64 t; cvta.to.shared.u64 t, %1; cvt.u32.u64 %0, t; }"
        : "=r"(a) : "l"(p));
    return a;
}
__device__ __forceinline__ void cpa16(uint32_t dst, const void* src) {
    asm volatile("cp.async.ca.shared.global [%0], [%1], 16;" :: "r"(dst), "l"(src));
}
__device__ __forceinline__ void cpa4(uint32_t dst, const void* src) {
    asm volatile("cp.async.ca.shared.global [%0], [%1], 4;" :: "r"(dst), "l"(src));
}

__global__ __launch_bounds__(64, 8)
void la_kernel(const float* __restrict__ qkv,
               const float* __restrict__ cw,
               const float* __restrict__ cb,
               float* __restrict__ out)
{
    // floats: [0,3812) = union{ qsm[49*36]+kT[32*64] | S[49*52] }
    __shared__ __align__(16) float sm[5896];
    float* qsm = sm;            // [49][QVS] token-major (raw q; scale on k)
    float* kT  = sm + 1764;     // [32][KS]  d-major, token blocks XOR-swizzled
    float* S   = sm;            // [49][SS]  aliases qsm/kT-head after phase 1
    float* vsm = sm + 3812;     // [49][QVS]
    float* wsm = sm + 5576;     // [9][32]
    float* bsm = sm + 5864;     // [32]

    const int tid = threadIdx.x;
    const int h   = blockIdx.y;
    const int win = blockIdx.x;
    const int b   = win >> 8;
    const int wy  = (win >> 4) & 15;
    const int wx  = win & 15;
    const int tok0  = b * 12544 + wy * 784 + wx * 7;
    const int cbase = h * 32;

    // 1/sqrt(32) * log2(e), folded into K during transpose-store
    const float scale = 0.17677669529663687f * 1.4426950408889634f;
    const size_t koff4 = 19267584ull;           // B*L*DIM/4 (float4 units)

    const uint32_t vsm_a = smem_u32(vsm);
    const uint32_t wsm_a = smem_u32(wsm);
    const uint32_t bsm_a = smem_u32(bsm);
    const uint32_t qsm_a = smem_u32(qsm);

    // ---- prologue: incremental addressing; q,v via cp.async; k via LDG ----
    // thread handles (tok = tb + 8*it, w = tid&7); per step: x+=1 (y+=1),
    // wrapping x 6->0 with an extra +105 tokens. Delta token = 113 or 218.
    const float4* qkv4 = (const float4*)qkv;
    {
        const int w = tid & 7;
        int tb = tid >> 3;                       // 0..7
        int x  = (tb < 7) ? tb : 0;              // tb==7 -> (y=1,x=0)
        int t  = (tb < 7) ? tb : 112;            // token index y*112+x
        uint32_t g = (uint32_t)(tok0 + t) * 96u + (uint32_t)(h * 8 + w);
        int tok = tb;
        const int pcol_hi = (w & 3);             // swizzle key for this w

        #pragma unroll
        for (int it = 0; it < 7; it++) {
            if (it < 6 || tid < 8) {
                uint32_t soff = (uint32_t)(tok * QVS + 4 * w) * 4u;
                cpa16(qsm_a + soff, qkv4 + g);                 // q raw
                cpa16(vsm_a + soff, qkv4 + g + 2 * koff4);     // v raw
                float4 k4 = qkv4[g + koff4];
                int d0 = 4 * w;
                int pcol = ((((tok >> 2) ^ pcol_hi) << 2)) | (tok & 3);
                kT[(d0    ) * KS + pcol] = k4.x * scale;
                kT[(d0 + 1) * KS + pcol] = k4.y * scale;
                kT[(d0 + 2) * KS + pcol] = k4.z * scale;
                kT[(d0 + 3) * KS + pcol] = k4.w * scale;
            }
            // advance (even on last iter; dead)
            uint32_t dg = (x == 6) ? (218u * 96u) : (113u * 96u);
            x = (x == 6) ? 0 : (x + 1);
            g += dg;
            tok += 8;
        }
    }
    for (int idx = tid; idx < 288; idx += 64) {
        int tap = idx >> 5, d = idx & 31;
        cpa4(wsm_a + (uint32_t)(tap * 32 + d) * 4u, cw + (cbase + d) * 9 + tap);
    }
    if (tid < 32) cpa4(bsm_a + tid * 4u, cb + cbase + tid);
    asm volatile("cp.async.commit_group;");
    asm volatile("cp.async.wait_group 0;" ::: "memory");
    __syncthreads();

    const int ti = tid >> 3;   // 0..7 (rows 7ti..7ti+6; ti==7 pad lane)
    const int tj = tid & 7;    // A cols 4tj..4tj+3; B cols 32+2tj..33+2tj
    const int rbase = (ti < 7) ? 7 * ti : 42;   // clamp pad lanes into qsm

    // ---- phase 1: S = q @ (k*scale)^T, cols 0..47, acc in regs ----
    u64 acc[7][3];   // [0]: cols 4tj,4tj+1  [1]: 4tj+2,4tj+3  [2]: 32+2tj,33+2tj
    #pragma unroll
    for (int r = 0; r < 7; r++)
        #pragma unroll
        for (int p = 0; p < 3; p++) acc[r][p] = 0ull;

    const float* qb = qsm + rbase * QVS;
    {
        const int bblk = 8 + (tj >> 1);         // logical 16B block of B col
        const int boff = (2 * tj) & 3;          // float offset within block
        #pragma unroll
        for (int dg = 0; dg < 8; dg++) {
            float4 q4[7];
            #pragma unroll
            for (int r = 0; r < 7; r++)
                q4[r] = *(const float4*)(qb + r * QVS + 4 * dg);
            const int key = dg & 3;
            const float* kbA = kT + ((tj ^ key) << 2);
            const float* kbB = kT + ((bblk ^ key) << 2) + boff;
            #pragma unroll
            for (int dd = 0; dd < 4; dd++) {
                const int drow = (4 * dg + dd) * KS;
                ulonglong2 ka = *(const ulonglong2*)(kbA + drow);
                u64 kb8 = *(const u64*)(kbB + drow);
                #pragma unroll
                for (int r = 0; r < 7; r++) {
                    float qv = (dd == 0) ? q4[r].x : (dd == 1) ? q4[r].y
                             : (dd == 2) ? q4[r].z : q4[r].w;
                    u64 q2 = pack2(qv, qv);
                    acc[r][0] = ffma2(q2, ka.x, acc[r][0]);
                    acc[r][1] = ffma2(q2, ka.y, acc[r][1]);
                    acc[r][2] = ffma2(q2, kb8, acc[r][2]);
                }
            }
        }
    }

    // ---- col 48: d-split across the 8 tj lanes, shfl reduce ----
    float s48[7];
    {
        const float* kc = kT + ((12 ^ (tj & 3)) << 2);   // logical block 12
        float k0 = kc[(4 * tj    ) * KS];
        float k1 = kc[(4 * tj + 1) * KS];
        float k2 = kc[(4 * tj + 2) * KS];
        float k3 = kc[(4 * tj + 3) * KS];
        #pragma unroll
        for (int r = 0; r < 7; r++) {
            float4 qq = *(const float4*)(qb + r * QVS + 4 * tj);
            float p = qq.x * k0 + qq.y * k1 + qq.z * k2 + qq.w * k3;
            p += __shfl_xor_sync(0xffffffffu, p, 1);
            p += __shfl_xor_sync(0xffffffffu, p, 2);
            p += __shfl_xor_sync(0xffffffffu, p, 4);
            s48[r] = p;
        }
    }
    __syncthreads();   // qsm/kT reads done (all warps); S may overwrite

    // ---- softmax: no max subtraction, packed normalize, float4 A-store ----
    {
        #pragma unroll
        for (int r = 0; r < 7; r++) {
            float s0, s1, s2, s3, s4, s5;
            unpack2(acc[r][0], s0, s1);
            unpack2(acc[r][1], s2, s3);
            unpack2(acc[r][2], s4, s5);
            float e0 = ex2(s0), e1 = ex2(s1);
            float e2 = ex2(s2), e3 = ex2(s3);
            float e4 = ex2(s4), e5 = ex2(s5);
            float e48 = ex2(s48[r]);
            float sum = ((e0 + e1) + (e2 + e3)) + (e4 + e5);
            sum += __shfl_xor_sync(0xffffffffu, sum, 1);
            sum += __shfl_xor_sync(0xffffffffu, sum, 2);
            sum += __shfl_xor_sync(0xffffffffu, sum, 4);
            sum += e48;                       // col 48, counted once
            float iv = rcp(sum);
            u64 iv2 = pack2(iv, iv);
            u64 p01 = mul2(pack2(e0, e1), iv2);
            u64 p23 = mul2(pack2(e2, e3), iv2);
            u64 p45 = mul2(pack2(e4, e5), iv2);
            if (ti < 7) {
                float* srow = S + (7 * ti + r) * SS;
                // group A: one 16B store (cols 4tj..4tj+3)
                ulonglong2 pa; pa.x = p01; pa.y = p23;
                *(ulonglong2*)(srow + 4 * tj) = pa;
                *(u64*)(srow + 32 + 2 * tj)   = p45;
                if (tj == 0) srow[48] = e48 * iv;
            }
        }
    }
    // S rows for this thread are produced by lanes of the SAME warp only
    __syncwarp();

    // ---- phase 2: out = S @ V + LePE(V) + bias ----
    {
        u64 att[7][2];
        float4 bb = *(const float4*)(bsm + tj * 4);
        u64 b01 = pack2(bb.x, bb.y), b23 = pack2(bb.z, bb.w);
        #pragma unroll
        for (int r = 0; r < 7; r++) { att[r][0] = b01; att[r][1] = b23; }

        // LePE with per-ny v-row register cache (7 rows loaded once per ky)
        #pragma unroll
        for (int ky = 0; ky < 3; ky++) {
            int ny = ti + ky - 1;
            if (ny >= 0 && ny <= 6) {
                ulonglong2 vc[7];
                #pragma unroll
                for (int rr = 0; rr < 7; rr++)
                    vc[rr] = *(const ulonglong2*)(vsm + (ny * 7 + rr) * QVS + tj * 4);
                #pragma unroll
                for (int kx = 0; kx < 3; kx++) {
                    const ulonglong2 w2 =
                        *(const ulonglong2*)(wsm + (ky * 3 + kx) * 32 + tj * 4);
                    #pragma unroll
                    for (int r = 0; r < 7; r++) {
                        int nx = r + kx - 1;
                        if (nx >= 0 && nx <= 6) {
                            att[r][0] = ffma2(w2.x, vc[nx].x, att[r][0]);
                            att[r][1] = ffma2(w2.y, vc[nx].y, att[r][1]);
                        }
                    }
                }
            }
        }

        // attention: k = 0..47 in 12 float4 groups (S already normalized)
        const float* Sb = S + rbase * SS;
        const float* vb = vsm + (tj << 2);
        #pragma unroll
        for (int kg = 0; kg < 12; kg++) {
            ulonglong2 v0 = *(const ulonglong2*)(vb + (4 * kg    ) * QVS);
            ulonglong2 v1 = *(const ulonglong2*)(vb + (4 * kg + 1) * QVS);
            ulonglong2 v2 = *(const ulonglong2*)(vb + (4 * kg + 2) * QVS);
            ulonglong2 v3 = *(const ulonglong2*)(vb + (4 * kg + 3) * QVS);
            #pragma unroll
            for (int r = 0; r < 7; r++) {
                float4 s4 = *(const float4*)(Sb + r * SS + 4 * kg);
                u64 p;
                p = pack2(s4.x, s4.x);
                att[r][0] = ffma2(p, v0.x, att[r][0]);
                att[r][1] = ffma2(p, v0.y, att[r][1]);
                p = pack2(s4.y, s4.y);
                att[r][0] = ffma2(p, v1.x, att[r][0]);
                att[r][1] = ffma2(p, v1.y, att[r][1]);
                p = pack2(s4.z, s4.z);
                att[r][0] = ffma2(p, v2.x, att[r][0]);
                att[r][1] = ffma2(p, v2.y, att[r][1]);
                p = pack2(s4.w, s4.w);
                att[r][0] = ffma2(p, v3.x, att[r][0]);
                att[r][1] = ffma2(p, v3.y, att[r][1]);
            }
        }
        // tail: k = 48
        {
            ulonglong2 vt = *(const ulonglong2*)(vb + 48 * QVS);
            #pragma unroll
            for (int r = 0; r < 7; r++) {
                float s = Sb[r * SS + 48];
                u64 p = pack2(s, s);
                att[r][0] = ffma2(p, vt.x, att[r][0]);
                att[r][1] = ffma2(p, vt.y, att[r][1]);
            }
        }

        if (ti < 7) {
            #pragma unroll
            for (int r = 0; r < 7; r++) {
                ulonglong2 o; o.x = att[r][0]; o.y = att[r][1];
                *(ulonglong2*)(out + (size_t)(tok0 + ti * 112 + r) * 384
                               + cbase + tj * 4) = o;
            }
        }
    }
}

extern "C" void kernel_launch(void* const* d_in, const int* in_sizes, int n_in,
                              void* d_out, int out_size)
{
    const float* qkv = (const float*)d_in[0];
    const float* cw  = (const float*)d_in[1];
    const float* cb  = (const float*)d_in[2];
    float* o = (float*)d_out;
    dim3 grid(4096, 12, 1);
    la_kernel<<<grid, 64>>>(qkv, cw, cb, o);
}